// round 11
// baseline (speedup 1.0000x reference)
#include <cuda_runtime.h>

// Problem constants (fixed by the reference)
#define BB     32
#define TXX    4096
#define DD     512
#define SPLITS 64
#define TCHUNK (TXX / SPLITS)   // 64
#define NT     256              // threads per ctx block (2 rows of D per iter)

// Per-batch 1/sum(mask) scratch (no cudaMalloc allowed)
__device__ float g_inv[BB];

// Kernel 0: per-batch mask count -> g_inv, and zero the context region of out.
__global__ void prep_kernel(const int* __restrict__ mask,
                            const int* __restrict__ um_p,
                            float* __restrict__ out) {
    const int b   = blockIdx.x;     // 32 blocks
    const int tid = threadIdx.x;    // 256 threads
    const bool um = (um_p[0] != 0);

    // Vectorized mask count: 4096 ints = 1024 int4 per batch
    const int4* m4 = (const int4*)(mask + b * TXX);
    int cnt = 0;
#pragma unroll
    for (int i = tid; i < TXX / 4; i += 256) {
        int4 v = m4[i];
        cnt += (v.x != 0) + (v.y != 0) + (v.z != 0) + (v.w != 0);
    }

    __shared__ int sdata[256];
    sdata[tid] = cnt;
    __syncthreads();
#pragma unroll
    for (int s = 128; s > 0; s >>= 1) {
        if (tid < s) sdata[tid] += sdata[tid + s];
        __syncthreads();
    }
    if (tid == 0) {
        int c = sdata[0] > 0 ? sdata[0] : 1;
        g_inv[b] = um ? (1.0f / (float)c) : 1.0f;
    }

    // Zero context region out[0 .. B*D) (d_out is poisoned 0xAA)
    for (int i = b * 256 + tid; i < BB * DD; i += 32 * 256)
        out[i] = 0.0f;
}

// Kernel 1: write alpha, compact kept rows (shared-atomic, order-free —
// ordering proven neutral in R7), masked row-sum with unconditional LDG.128
// (unroll 8 -> deep MLP), SMEM half-reduction, then global atomics.
// Grid: (SPLITS, BB) = 2048 blocks for fine-grained load balance.
// Thread -> (half = tid>>7, col = tid&127).
__global__ void __launch_bounds__(NT)
ctx_alpha_kernel(const float* __restrict__ a,
                 const int* __restrict__ mask,
                 const int* __restrict__ um_p,
                 float* __restrict__ out) {
    const int s   = blockIdx.x;
    const int b   = blockIdx.y;
    const int tid = threadIdx.x;
    const bool um = (um_p[0] != 0);
    const float inv = g_inv[b];
    const int t0 = s * TCHUNK;

    __shared__ int    slist[TCHUNK];
    __shared__ int    scnt;
    __shared__ float4 sctx[DD / 4];   // 128 float4

    if (tid == 0) scnt = 0;
    __syncthreads();

    // Stage: one thread per t in this chunk. Write alpha; compact kept indices.
    float* alpha = out + BB * DD + (size_t)b * TXX;
    if (tid < TCHUNK) {
        int t = t0 + tid;
        int m = (mask[b * TXX + t] != 0);
        int keep = um ? m : 1;
        alpha[t] = um ? (m ? inv : 0.0f) : 1.0f;
        if (keep) {
            int p = atomicAdd(&scnt, 1);
            slist[p] = tid;
        }
    }
    __syncthreads();

    const int n    = scnt;
    const int col  = tid & 127;
    const int half = tid >> 7;

    // Unconditional loads over the compacted list -> front-batched LDG.128.
    // unroll 8: 8 independent loads in flight per thread.
    const float4* abase = (const float4*)(a + ((size_t)b * TXX + t0) * DD);
    float4 acc = make_float4(0.f, 0.f, 0.f, 0.f);
#pragma unroll 8
    for (int i = half; i < n; i += 2) {
        int t = slist[i];                       // LDS broadcast within warp
        float4 v = abase[(size_t)t * (DD / 4) + col];
        acc.x += v.x; acc.y += v.y; acc.z += v.z; acc.w += v.w;
    }

    // Reduce the two halves through SMEM, then half 1 issues the atomics.
    if (half == 0) sctx[col] = acc;
    __syncthreads();
    if (half == 1) {
        float4 o = sctx[col];
        acc.x += o.x; acc.y += o.y; acc.z += o.z; acc.w += o.w;
        float* ctx = out + (size_t)b * DD + col * 4;
        atomicAdd(ctx + 0, acc.x * inv);
        atomicAdd(ctx + 1, acc.y * inv);
        atomicAdd(ctx + 2, acc.z * inv);
        atomicAdd(ctx + 3, acc.w * inv);
    }
}

extern "C" void kernel_launch(void* const* d_in, const int* in_sizes, int n_in,
                              void* d_out, int out_size) {
    // metadata order: a, h, coverage, X_mask, Wa, Wh, Wc, V, use_coverage, use_masking
    const float* a    = (const float*)d_in[0];
    const int*   mask = (const int*)  d_in[3];
    const int*   um   = (const int*)  d_in[9];
    float* out = (float*)d_out;

    prep_kernel<<<BB, 256>>>(mask, um, out);
    dim3 grid(SPLITS, BB);
    ctx_alpha_kernel<<<grid, NT>>>(a, mask, um, out);
}

// round 12
// speedup vs baseline: 1.2281x; 1.2281x over previous
#include <cuda_runtime.h>

// Problem constants (fixed by the reference)
#define BB     32
#define TXX    4096
#define DD     512
#define SPLITS 32
#define TCHUNK (TXX / SPLITS)   // 128
#define NT     256              // threads per ctx block (2 rows of D per iter)
#define QS     8                // alpha chunks per batch in finish kernel

// Scratch (no cudaMalloc allowed): per-(b,s) unscaled partial sums + counts.
__device__ float g_part[BB * SPLITS * DD];   // 2 MB, fully overwritten each call
__device__ int   g_cnt[BB * SPLITS];

// Kernel 1: compact kept rows (shared-atomic — ordering proven neutral in R7),
// masked row-sum with unconditional LDG.128 (unroll 4 — proven R4 mainloop),
// SMEM half-reduction, then PLAIN stores of the unscaled partial into the
// block-owned slice of g_part. No dependency on any other kernel -> starts
// immediately; no global atomics; no zero-init of the output needed here.
// Grid: (SPLITS, BB), NT=256; thread -> (half = tid>>7, col = tid&127).
__global__ void __launch_bounds__(NT)
ctx_partial_kernel(const float* __restrict__ a,
                   const int* __restrict__ mask,
                   const int* __restrict__ um_p) {
    const int s   = blockIdx.x;
    const int b   = blockIdx.y;
    const int tid = threadIdx.x;
    const bool um = (um_p[0] != 0);
    const int t0 = s * TCHUNK;

    __shared__ int    slist[TCHUNK];
    __shared__ int    scnt;
    __shared__ float4 sctx[DD / 4];   // 128 float4

    if (tid == 0) scnt = 0;
    __syncthreads();

    // Stage: one thread per t in this chunk; compact kept indices.
    if (tid < TCHUNK) {
        int m = (mask[b * TXX + t0 + tid] != 0);
        int keep = um ? m : 1;
        if (keep) {
            int p = atomicAdd(&scnt, 1);
            slist[p] = tid;
        }
    }
    __syncthreads();

    const int n    = scnt;
    const int col  = tid & 127;
    const int half = tid >> 7;

    // Unconditional loads over the compacted list -> front-batched LDG.128.
    const float4* abase = (const float4*)(a + ((size_t)b * TXX + t0) * DD);
    float4 acc = make_float4(0.f, 0.f, 0.f, 0.f);
#pragma unroll 4
    for (int i = half; i < n; i += 2) {
        int t = slist[i];                       // LDS broadcast within warp
        float4 v = abase[(size_t)t * (DD / 4) + col];
        acc.x += v.x; acc.y += v.y; acc.z += v.z; acc.w += v.w;
    }

    // Reduce the two halves through SMEM; half 1 stores the unscaled partial.
    if (half == 0) sctx[col] = acc;
    __syncthreads();
    if (half == 1) {
        float4 o = sctx[col];
        acc.x += o.x; acc.y += o.y; acc.z += o.z; acc.w += o.w;
        float4* part = (float4*)(g_part + ((size_t)b * SPLITS + s) * DD);
        part[col] = acc;                        // plain STG.128, block-owned
        if (col == 0) g_cnt[b * SPLITS + s] = n;
    }
}

// Kernel 2: per (q, b) block. Sum the 32 chunk counts -> inv; write the alpha
// chunk; block q==0 additionally reduces the 32 partials into context.
// Grid: (QS, BB), 256 threads. ~3 MB of mostly-L2-resident traffic.
__global__ void __launch_bounds__(256)
finish_kernel(const int* __restrict__ mask,
              const int* __restrict__ um_p,
              float* __restrict__ out) {
    const int q   = blockIdx.x;
    const int b   = blockIdx.y;
    const int tid = threadIdx.x;
    const bool um = (um_p[0] != 0);

    __shared__ float sinv;
    if (tid < 32) {
        int c = g_cnt[b * SPLITS + tid];
#pragma unroll
        for (int o = 16; o > 0; o >>= 1)
            c += __shfl_down_sync(0xffffffffu, c, o);
        if (tid == 0) sinv = um ? (1.0f / (float)(c > 0 ? c : 1)) : 1.0f;
    }
    __syncthreads();
    const float inv = sinv;

    // Alpha chunk: 512 t's per (q,b).
    const int t0 = q * (TXX / QS);
    float* alpha = out + BB * DD + (size_t)b * TXX;
#pragma unroll
    for (int t = tid; t < TXX / QS; t += 256) {
        int m = (mask[b * TXX + t0 + t] != 0);
        alpha[t0 + t] = um ? (m ? inv : 0.0f) : 1.0f;
    }

    // Context: q==0 block reduces the 32 partials for this batch.
    if (q == 0) {
        const float* pb = g_part + (size_t)b * SPLITS * DD;
#pragma unroll
        for (int d = tid; d < DD; d += 256) {
            float sum = 0.0f;
#pragma unroll
            for (int s2 = 0; s2 < SPLITS; s2++)
                sum += pb[s2 * DD + d];
            out[b * DD + d] = sum * inv;
        }
    }
}

extern "C" void kernel_launch(void* const* d_in, const int* in_sizes, int n_in,
                              void* d_out, int out_size) {
    // metadata order: a, h, coverage, X_mask, Wa, Wh, Wc, V, use_coverage, use_masking
    const float* a    = (const float*)d_in[0];
    const int*   mask = (const int*)  d_in[3];
    const int*   um   = (const int*)  d_in[9];
    float* out = (float*)d_out;

    dim3 grid1(SPLITS, BB);
    ctx_partial_kernel<<<grid1, NT>>>(a, mask, um);
    dim3 grid2(QS, BB);
    finish_kernel<<<grid2, 256>>>(mask, um, out);
}